// round 9
// baseline (speedup 1.0000x reference)
#include <cuda_runtime.h>
#include <cuda_fp16.h>
#include <cstdint>

#define TOKENS 16384
#define HIDDEN 2048
#define NEXP   128
#define NOUT   256
#define TOPK   8
#define NCAND  32
#define TAU_L  6e-5f

typedef unsigned long long u64;

// ---------------- scratch (no allocs allowed) ----------------
__device__ float g_wT[HIDDEN * NOUT];        // [h][n] fp32 (certified recompute)
__device__ float g_logits[TOKENS * NOUT];    // only for flagged tokens (recompute)
// planes packed: xp0 | xp1 | wp0 | wp1
#define XP0_OFF 0
#define XP1_OFF ((size_t)TOKENS * HIDDEN)
#define WP0_OFF ((size_t)2 * TOKENS * HIDDEN)
#define WP1_OFF ((size_t)2 * TOKENS * HIDDEN + (size_t)NOUT * HIDDEN)
__device__ __half g_planes[2 * (size_t)TOKENS * HIDDEN + 2 * (size_t)NOUT * HIDDEN];
__device__ int g_nflag;
__device__ int g_flags[TOKENS];

// ---------------- PTX helpers (baseline ISA only) ----------------
__device__ __forceinline__ uint32_t smem_u32(const void* p) {
    uint32_t a;
    asm("{ .reg .u64 t; cvta.to.shared.u64 t, %1; cvt.u32.u64 %0, t; }" : "=r"(a) : "l"(p));
    return a;
}
__device__ __forceinline__ void cp16s(uint32_t saddr, const void* g) {
    asm volatile("cp.async.cg.shared.global [%0], [%1], 16;" :: "r"(saddr), "l"(g));
}
__device__ __forceinline__ void ldsm4(uint32_t* r, uint32_t a) {
    asm volatile("ldmatrix.sync.aligned.m8n8.x4.shared.b16 {%0,%1,%2,%3}, [%4];"
                 : "=r"(r[0]), "=r"(r[1]), "=r"(r[2]), "=r"(r[3]) : "r"(a));
}
__device__ __forceinline__ void mma16816(float* d, const uint32_t* a, const uint32_t* b) {
    asm volatile(
        "mma.sync.aligned.m16n8k16.row.col.f32.f16.f16.f32 "
        "{%0,%1,%2,%3}, {%4,%5,%6,%7}, {%8,%9}, {%0,%1,%2,%3};"
        : "+f"(d[0]), "+f"(d[1]), "+f"(d[2]), "+f"(d[3])
        : "r"(a[0]), "r"(a[1]), "r"(a[2]), "r"(a[3]), "r"(b[0]), "r"(b[1]));
}
#define GBAR(g) asm volatile("bar.sync %0, %1;" :: "r"((g) + 1), "r"(128) : "memory")

// ---------------------------------------------------------------------------
// fp16 2-plane split: v = p0 + p1 + O(2^-22 v)
// ---------------------------------------------------------------------------
__device__ __forceinline__ void split2(float v, __half& a0, __half& a1) {
    a0 = __float2half_rn(v);
    a1 = __float2half_rn(v - __half2float(a0));
}

// ---------------------------------------------------------------------------
// Weight prep: fp16 planes + fp32 transpose + flag reset (one kernel)
// ---------------------------------------------------------------------------
__global__ void wprep_kernel(const float* __restrict__ wo,
                             const float* __restrict__ wb) {
    if (blockIdx.x == 0 && threadIdx.x == 0) g_nflag = 0;
    size_t i4 = (size_t)blockIdx.x * 256 + threadIdx.x;     // float4 over [256][2048]
    if (i4 >= (size_t)NOUT * HIDDEN / 4) return;
    int n  = (int)(i4 / (HIDDEN / 4));
    int c4 = (int)(i4 % (HIDDEN / 4)) * 4;
    const float* src = (n < NEXP) ? &wo[(size_t)n * HIDDEN + c4]
                                  : &wb[(size_t)(n - NEXP) * HIDDEN + c4];
    float4 v = *(const float4*)src;
    __half a0[4], a1[4];
    split2(v.x, a0[0], a1[0]);
    split2(v.y, a0[1], a1[1]);
    split2(v.z, a0[2], a1[2]);
    split2(v.w, a0[3], a1[3]);
    size_t e = (size_t)n * HIDDEN + c4;
    *(uint2*)&g_planes[WP0_OFF + e] = *(uint2*)a0;
    *(uint2*)&g_planes[WP1_OFF + e] = *(uint2*)a1;
    // fp32 transpose for certified recompute
    g_wT[(size_t)(c4 + 0) * NOUT + n] = v.x;
    g_wT[(size_t)(c4 + 1) * NOUT + n] = v.y;
    g_wT[(size_t)(c4 + 2) * NOUT + n] = v.z;
    g_wT[(size_t)(c4 + 3) * NOUT + n] = v.w;
}

__global__ void xsplit_kernel(const float* __restrict__ x) {
    size_t i4 = (size_t)blockIdx.x * 256 + threadIdx.x;
    float4 v = ((const float4*)x)[i4];
    __half a0[4], a1[4];
    split2(v.x, a0[0], a1[0]);
    split2(v.y, a0[1], a1[1]);
    split2(v.z, a0[2], a1[2]);
    split2(v.w, a0[3], a1[3]);
    size_t e = i4 * 4;
    *(uint2*)&g_planes[XP0_OFF + e] = *(uint2*)a0;
    *(uint2*)&g_planes[XP1_OFF + e] = *(uint2*)a1;
}

// ---------------------------------------------------------------------------
// Precise exp + warp reductions
// ---------------------------------------------------------------------------
__device__ __forceinline__ float exp_precise(float xx) {
    float kf = rintf(xx * 1.4426950408889634f);
    float r  = fmaf(kf, -0.693145751953125f, xx);
    r = fmaf(kf, -1.42860676533018704e-06f, r);
    float p = 1.98412698412698413e-04f;
    p = fmaf(p, r, 1.38888888888888889e-03f);
    p = fmaf(p, r, 8.33333333333333333e-03f);
    p = fmaf(p, r, 4.16666666666666667e-02f);
    p = fmaf(p, r, 1.66666666666666667e-01f);
    p = fmaf(p, r, 0.5f);
    p = fmaf(p, r, 1.0f);
    p = fmaf(p, r, 1.0f);
    int ki = (int)kf;
    return p * __int_as_float((ki + 127) << 23);
}
__device__ __forceinline__ float warpMax(float v) {
#pragma unroll
    for (int o = 16; o; o >>= 1) v = fmaxf(v, __shfl_xor_sync(0xffffffffu, v, o));
    return v;
}
__device__ __forceinline__ float warpSum(float v) {
#pragma unroll
    for (int o = 16; o; o >>= 1) v += __shfl_xor_sync(0xffffffffu, v, o);
    return v;
}

// ---------------------------------------------------------------------------
// Fused GEMM + routing. CTA = 128 tokens x 256 experts, 512 threads (4x4 warps).
// Per-accumulator MMA order identical to the certified round-8 kernel.
// Stage: BK=32 halves, rows padded to 80B. Single-sync double-buffer pipeline.
// Epilogue -> smem logits -> 4 groups of 128 threads route 32 tokens each.
// ---------------------------------------------------------------------------
#define ROWB    80
#define SROWS   768                   // 2*128 A rows + 2*256 B rows
#define STAGEB  (SROWS * ROWB)        // 61440 B
#define NKB     (HIDDEN / 32)         // 64 stages
#define SLSTR   258                   // smem logits row stride (floats)
#define DSMEM   (128 * SLSTR * 4)     // 132096 B >= 2*STAGEB

__global__ __launch_bounds__(512, 1) void fused_kernel(float* __restrict__ out) {
    extern __shared__ char dsm[];
    const uint32_t sbase = smem_u32(dsm);
    float* slog = (float*)dsm;

    const int tid    = threadIdx.x;
    const int lane   = tid & 31;
    const int wid    = tid >> 5;
    const int warp_m = wid & 3;
    const int warp_n = wid >> 2;     // 0..3
    const int m0     = blockIdx.x * 128;

    // ---- per-thread loader setup: 6 chunks (3072 per stage / 512 threads) ----
    uint32_t soff[6], goff[6];
#pragma unroll
    for (int i = 0; i < 6; ++i) {
        int cid = tid + i * 512;
        int row = cid >> 2;
        int seg = cid & 3;
        soff[i] = row * ROWB + seg * 16;
        size_t go;
        if (row < 256) {            // A planes
            int p = row >> 7, r = row & 127;
            go = (p ? XP1_OFF : XP0_OFF) + (size_t)(m0 + r) * HIDDEN + seg * 8;
        } else {                    // B planes
            int q = (row - 256) >> 8, r = (row - 256) & 255;
            go = (q ? WP1_OFF : WP0_OFF) + (size_t)r * HIDDEN + seg * 8;
        }
        goff[i] = (uint32_t)(go * 2);   // bytes
    }
    const char* gbase = (const char*)g_planes;

    float acc[2][8][4];
#pragma unroll
    for (int mf = 0; mf < 2; ++mf)
#pragma unroll
        for (int nf = 0; nf < 8; ++nf)
#pragma unroll
            for (int c = 0; c < 4; ++c) acc[mf][nf][c] = 0.f;

    const int a_row = lane & 15;
    const int a_col = (lane >> 4) << 3;
    const int b_row = ((lane >> 4) & 1) * 8 + (lane & 7);
    const int b_col = ((lane >> 3) & 1) * 8;

    // preload stage 0
#pragma unroll
    for (int i = 0; i < 6; ++i) cp16s(sbase + soff[i], gbase + goff[i]);
    asm volatile("cp.async.commit_group;");

    for (int kb = 0; kb < NKB; ++kb) {
        const uint32_t cur = sbase + (kb & 1) * STAGEB;
        asm volatile("cp.async.wait_group 0;");
        __syncthreads();
        if (kb + 1 < NKB) {
            const uint32_t nxt = sbase + ((kb + 1) & 1) * STAGEB;
            const uint32_t kadd = (uint32_t)(kb + 1) * 64;   // bytes per stage step
#pragma unroll
            for (int i = 0; i < 6; ++i) cp16s(nxt + soff[i], gbase + goff[i] + kadd);
            asm volatile("cp.async.commit_group;");
        }

#pragma unroll
        for (int s = 0; s < 2; ++s) {
            uint32_t af[2][2][4];
#pragma unroll
            for (int p = 0; p < 2; ++p)
#pragma unroll
                for (int mf = 0; mf < 2; ++mf) {
                    uint32_t addr = cur
                                  + (p * 128 + warp_m * 32 + mf * 16 + a_row) * ROWB
                                  + (s * 16 + a_col) * 2;
                    ldsm4(af[p][mf], addr);
                }
#pragma unroll
            for (int pb = 0; pb < 2; ++pb) {
                uint32_t bf[4][4];
#pragma unroll
                for (int np = 0; np < 4; ++np) {
                    uint32_t addr = cur
                                  + (256 + pb * 256 + warp_n * 64 + np * 16 + b_row) * ROWB
                                  + (s * 16 + b_col) * 2;
                    ldsm4(bf[np], addr);
                }
                const int na = 2 - pb;
#pragma unroll
                for (int pa = 0; pa < 2; ++pa) {
                    if (pa >= na) break;
#pragma unroll
                    for (int mf = 0; mf < 2; ++mf)
#pragma unroll
                        for (int nf = 0; nf < 8; ++nf)
                            mma16816(acc[mf][nf], af[pa][mf], &bf[nf >> 1][(nf & 1) * 2]);
                }
            }
        }
    }

    // ---- epilogue: accs -> smem logits ----
    __syncthreads();   // all reads of stage buffers done before overwrite
#pragma unroll
    for (int mf = 0; mf < 2; ++mf)
#pragma unroll
        for (int nf = 0; nf < 8; ++nf) {
            const int row = warp_m * 32 + mf * 16 + (lane >> 2);
            const int col = warp_n * 64 + nf * 8 + (lane & 3) * 2;
            *(float2*)&slog[(size_t)row * SLSTR + col] =
                make_float2(acc[mf][nf][0], acc[mf][nf][1]);
            *(float2*)&slog[(size_t)(row + 8) * SLSTR + col] =
                make_float2(acc[mf][nf][2], acc[mf][nf][3]);
        }
    __syncthreads();

    // ---- routing: group g (128 threads) handles tokens g*32 .. g*32+31 ----
    const int g  = tid >> 7;
    const int e  = tid & 127;
    const int gw = (tid >> 5) & 3;
    const int gl = tid & 31;

    __shared__ float s4g[4][4];
    __shared__ float sbg[4][NEXP];
    __shared__ float bvhlg[4][NEXP];
    __shared__ float candpg[4][NCAND];
    __shared__ float candflg[4][NCAND];
    __shared__ int   candeg[4][NCAND];
    __shared__ float candlg[4][NCAND];
    __shared__ float toppg[4][TOPK];
    __shared__ int   topeg[4][TOPK];

    for (int it = 0; it < 32; ++it) {
        const int t  = g * 32 + it;
        const int tg = m0 + t;
        float fl = slog[(size_t)t * SLSTR + e];
        float bl = slog[(size_t)t * SLSTR + 128 + e];

        // ---- full softmax ----
        float wm = warpMax(fl);
        if (gl == 0) s4g[g][gw] = wm;
        GBAR(g);
        float m1 = fmaxf(fmaxf(s4g[g][0], s4g[g][1]), fmaxf(s4g[g][2], s4g[g][3]));
        GBAR(g);
        float p = exp_precise(fl - m1);
        float wsum = warpSum(p);
        if (gl == 0) s4g[g][gw] = wsum;
        GBAR(g);
        float s1 = s4g[g][0] + s4g[g][1] + s4g[g][2] + s4g[g][3];
        GBAR(g);
        float prob = __fdiv_rn(p, s1);
        out[(size_t)tg * NEXP + e] = prob;

        // ---- bvh softmax ----
        wm = warpMax(bl);
        if (gl == 0) s4g[g][gw] = wm;
        GBAR(g);
        float m2 = fmaxf(fmaxf(s4g[g][0], s4g[g][1]), fmaxf(s4g[g][2], s4g[g][3]));
        GBAR(g);
        float q = exp_precise(bl - m2);
        wsum = warpSum(q);
        if (gl == 0) s4g[g][gw] = wsum;
        GBAR(g);
        float s2 = s4g[g][0] + s4g[g][1] + s4g[g][2] + s4g[g][3];
        float bprob = __fdiv_rn(q, s2);
        sbg[g][e] = bprob;
        GBAR(g);

        // ---- rank by bvh prob ----
        int r = 0;
#pragma unroll 8
        for (int j = 0; j < NEXP; ++j) {
            float v = sbg[g][j];
            r += (v > bprob) || (v == bprob && j < e);
        }
        bvhlg[g][r] = bl;
        if (r < NCAND) { candeg[g][r] = e; candpg[g][r] = prob; candflg[g][r] = fl; }
        GBAR(g);

        // ---- top-8 among 32 candidates ----
        if (e < NCAND) {
            float cp = candpg[g][e];
            int r2 = 0;
#pragma unroll
            for (int j = 0; j < NCAND; ++j) {
                float v = candpg[g][j];
                r2 += (v > cp) || (v == cp && j < e);
            }
            candlg[g][r2] = candflg[g][e];
            if (r2 < TOPK) { topeg[g][r2] = candeg[g][e]; toppg[g][r2] = cp; }
        }
        GBAR(g);

        // ---- renormalize + write + audit ----
        if (e == 0) {
            float s = 0.f;
#pragma unroll
            for (int k = 0; k < TOPK; ++k) s += toppg[g][k];
            float* ov = out + (size_t)TOKENS * NEXP + (size_t)tg * TOPK;
            float* oi = out + (size_t)TOKENS * NEXP + (size_t)TOKENS * TOPK + (size_t)tg * TOPK;
#pragma unroll
            for (int k = 0; k < TOPK; ++k) {
                ov[k] = __fdiv_rn(toppg[g][k], s);
                oi[k] = (float)topeg[g][k];
            }
            bool flag = (bvhlg[g][NCAND - 1] - bvhlg[g][NCAND] < TAU_L) ||
                        (candlg[g][TOPK - 1] - candlg[g][TOPK] < TAU_L);
#pragma unroll
            for (int k = 0; k < TOPK - 1; ++k)
                flag |= (candlg[g][k] - candlg[g][k + 1] < TAU_L);
            if (flag) {
                int pos = atomicAdd(&g_nflag, 1);
                g_flags[pos] = tg;
            }
        }
        GBAR(g);
    }
}

// ---------------------------------------------------------------------------
// Certified recompute (bitwise == round-2 chain) for flagged tokens.
// ---------------------------------------------------------------------------
__global__ __launch_bounds__(256) void recompute_kernel(const float* __restrict__ x) {
    const int n = threadIdx.x;
    const int cnt = g_nflag;
    for (int i = blockIdx.x; i < cnt; i += gridDim.x) {
        const int t = g_flags[i];
        const float* xr = x + (size_t)t * HIDDEN;
        float acc = 0.f, cmp = 0.f;
        for (int kb = 0; kb < HIDDEN; kb += 16) {
            float bp = 0.f;
#pragma unroll
            for (int k = 0; k < 16; ++k)
                bp = fmaf(xr[kb + k], g_wT[(size_t)(kb + k) * NOUT + n], bp);
            float y = bp - cmp;
            float s = acc + y;
            cmp = (s - acc) - y;
            acc = s;
        }
        g_logits[(size_t)t * NOUT + n] = acc;
    }
}

// ---------------------------------------------------------------------------
// Re-route flagged tokens from certified logits in g_logits.
// ---------------------------------------------------------------------------
__global__ __launch_bounds__(128) void route_flagged_kernel(float* __restrict__ out) {
    const int e = threadIdx.x;
    const int wid = e >> 5;
    const int lane = e & 31;
    const int cnt = g_nflag;

    __shared__ float s4[4];
    __shared__ float sb[NEXP];
    __shared__ float cand_p[NCAND];
    __shared__ int   cand_e[NCAND];
    __shared__ float top_p[TOPK];
    __shared__ int   top_e[TOPK];

    for (int i = blockIdx.x; i < cnt; i += gridDim.x) {
        const int t = g_flags[i];
        float fl = g_logits[(size_t)t * NOUT + e];
        float bl = g_logits[(size_t)t * NOUT + NEXP + e];

        float wm = warpMax(fl);
        if (lane == 0) s4[wid] = wm;
        __syncthreads();
        float m1 = fmaxf(fmaxf(s4[0], s4[1]), fmaxf(s4[2], s4[3]));
        __syncthreads();
        float p = exp_precise(fl - m1);
        float wsum = warpSum(p);
        if (lane == 0) s4[wid] = wsum;
        __syncthreads();
        float s1 = s4[0] + s4[1] + s4[2] + s4[3];
        __syncthreads();
        float prob = __fdiv_rn(p, s1);
        out[(size_t)t * NEXP + e] = prob;

        wm = warpMax(bl);
        if (lane == 0) s4[wid] = wm;
        __syncthreads();
        float m2 = fmaxf(fmaxf(s4[0], s4[1]), fmaxf(s4[2], s4[3]));
        __syncthreads();
        float q = exp_precise(bl - m2);
        wsum = warpSum(q);
        if (lane == 0) s4[wid] = wsum;
        __syncthreads();
        float s2 = s4[0] + s4[1] + s4[2] + s4[3];
        float bprob = __fdiv_rn(q, s2);
        sb[e] = bprob;
        __syncthreads();

        int r = 0;
#pragma unroll 8
        for (int j = 0; j < NEXP; ++j) {
            float v = sb[j];
            r += (v > bprob) || (v == bprob && j < e);
        }
        if (r < NCAND) { cand_e[r] = e; cand_p[r] = prob; }
        __syncthreads();

        if (e < NCAND) {
            float cp = cand_p[e];
            int r2 = 0;
#pragma unroll
            for (int j = 0; j < NCAND; ++j) {
                float v = cand_p[j];
                r2 += (v > cp) || (v == cp && j < e);
            }
            if (r2 < TOPK) { top_e[r2] = cand_e[e]; top_p[r2] = cp; }
        }
        __syncthreads();

        if (e == 0) {
            float s = 0.f;
#pragma unroll
            for (int k = 0; k < TOPK; ++k) s += top_p[k];
            float* ov = out + (size_t)TOKENS * NEXP + (size_t)t * TOPK;
            float* oi = out + (size_t)TOKENS * NEXP + (size_t)TOKENS * TOPK + (size_t)t * TOPK;
#pragma unroll
            for (int k = 0; k < TOPK; ++k) {
                ov[k] = __fdiv_rn(top_p[k], s);
                oi[k] = (float)top_e[k];
            }
        }
        __syncthreads();
    }
}

// ---------------------------------------------------------------------------
extern "C" void kernel_launch(void* const* d_in, const int* in_sizes, int n_in,
                              void* d_out, int out_size) {
    const float* x  = (const float*)d_in[0];   // [16384, 2048]
    const float* wo = (const float*)d_in[1];   // [128, 2048]
    const float* wb = (const float*)d_in[2];   // [128, 2048]
    float* out = (float*)d_out;

    cudaFuncSetAttribute(fused_kernel, cudaFuncAttributeMaxDynamicSharedMemorySize, DSMEM);

    wprep_kernel<<<(NOUT * HIDDEN / 4 + 255) / 256, 256>>>(wo, wb);
    xsplit_kernel<<<TOKENS * HIDDEN / 4 / 256, 256>>>(x);
    fused_kernel<<<TOKENS / 128, 512, DSMEM>>>(out);
    recompute_kernel<<<1024, 256>>>(x);
    route_flagged_kernel<<<1024, 128>>>(out);
}

// round 10
// speedup vs baseline: 1.2529x; 1.2529x over previous
#include <cuda_runtime.h>
#include <cuda_fp16.h>
#include <cstdint>

#define TOKENS 16384
#define HIDDEN 2048
#define NEXP   128
#define NOUT   256
#define TOPK   8
#define NCAND  32
#define TAU_L  6e-5f

typedef unsigned long long u64;

// ---------------- scratch (no allocs allowed) ----------------
__device__ float g_wT[HIDDEN * NOUT];        // [h][n] fp32 (certified recompute)
// planes packed: xp0 | xp1 | wp0 | wp1
#define XP0_OFF 0
#define XP1_OFF ((size_t)TOKENS * HIDDEN)
#define WP0_OFF ((size_t)2 * TOKENS * HIDDEN)
#define WP1_OFF ((size_t)2 * TOKENS * HIDDEN + (size_t)NOUT * HIDDEN)
__device__ __half g_planes[2 * (size_t)TOKENS * HIDDEN + 2 * (size_t)NOUT * HIDDEN];
__device__ int g_nflag;
__device__ int g_flags[TOKENS];

// ---------------- PTX helpers (baseline ISA only) ----------------
__device__ __forceinline__ uint32_t smem_u32(const void* p) {
    uint32_t a;
    asm("{ .reg .u64 t; cvta.to.shared.u64 t, %1; cvt.u32.u64 %0, t; }" : "=r"(a) : "l"(p));
    return a;
}
__device__ __forceinline__ void cp16s(uint32_t saddr, const void* g) {
    asm volatile("cp.async.cg.shared.global [%0], [%1], 16;" :: "r"(saddr), "l"(g));
}
__device__ __forceinline__ void ldsm4(uint32_t* r, uint32_t a) {
    asm volatile("ldmatrix.sync.aligned.m8n8.x4.shared.b16 {%0,%1,%2,%3}, [%4];"
                 : "=r"(r[0]), "=r"(r[1]), "=r"(r[2]), "=r"(r[3]) : "r"(a));
}
__device__ __forceinline__ void mma16816(float* d, const uint32_t* a, const uint32_t* b) {
    asm volatile(
        "mma.sync.aligned.m16n8k16.row.col.f32.f16.f16.f32 "
        "{%0,%1,%2,%3}, {%4,%5,%6,%7}, {%8,%9}, {%0,%1,%2,%3};"
        : "+f"(d[0]), "+f"(d[1]), "+f"(d[2]), "+f"(d[3])
        : "r"(a[0]), "r"(a[1]), "r"(a[2]), "r"(a[3]), "r"(b[0]), "r"(b[1]));
}
#define GBAR(g) asm volatile("bar.sync %0, %1;" :: "r"((g) + 1), "r"(128) : "memory")

// ---------------------------------------------------------------------------
// fp16 2-plane split: v = p0 + p1 + O(2^-22 v)
// ---------------------------------------------------------------------------
__device__ __forceinline__ void split2(float v, __half& a0, __half& a1) {
    a0 = __float2half_rn(v);
    a1 = __float2half_rn(v - __half2float(a0));
}

__global__ void wprep_kernel(const float* __restrict__ wo,
                             const float* __restrict__ wb) {
    if (blockIdx.x == 0 && threadIdx.x == 0) g_nflag = 0;
    size_t i4 = (size_t)blockIdx.x * 256 + threadIdx.x;
    if (i4 >= (size_t)NOUT * HIDDEN / 4) return;
    int n  = (int)(i4 / (HIDDEN / 4));
    int c4 = (int)(i4 % (HIDDEN / 4)) * 4;
    const float* src = (n < NEXP) ? &wo[(size_t)n * HIDDEN + c4]
                                  : &wb[(size_t)(n - NEXP) * HIDDEN + c4];
    float4 v = *(const float4*)src;
    __half a0[4], a1[4];
    split2(v.x, a0[0], a1[0]);
    split2(v.y, a0[1], a1[1]);
    split2(v.z, a0[2], a1[2]);
    split2(v.w, a0[3], a1[3]);
    size_t e = (size_t)n * HIDDEN + c4;
    *(uint2*)&g_planes[WP0_OFF + e] = *(uint2*)a0;
    *(uint2*)&g_planes[WP1_OFF + e] = *(uint2*)a1;
    g_wT[(size_t)(c4 + 0) * NOUT + n] = v.x;
    g_wT[(size_t)(c4 + 1) * NOUT + n] = v.y;
    g_wT[(size_t)(c4 + 2) * NOUT + n] = v.z;
    g_wT[(size_t)(c4 + 3) * NOUT + n] = v.w;
}

__global__ void xsplit_kernel(const float* __restrict__ x) {
    size_t i4 = (size_t)blockIdx.x * 256 + threadIdx.x;
    float4 v = ((const float4*)x)[i4];
    __half a0[4], a1[4];
    split2(v.x, a0[0], a1[0]);
    split2(v.y, a0[1], a1[1]);
    split2(v.z, a0[2], a1[2]);
    split2(v.w, a0[3], a1[3]);
    size_t e = i4 * 4;
    *(uint2*)&g_planes[XP0_OFF + e] = *(uint2*)a0;
    *(uint2*)&g_planes[XP1_OFF + e] = *(uint2*)a1;
}

// ---------------------------------------------------------------------------
// Precise exp + warp reductions
// ---------------------------------------------------------------------------
__device__ __forceinline__ float exp_precise(float xx) {
    float kf = rintf(xx * 1.4426950408889634f);
    float r  = fmaf(kf, -0.693145751953125f, xx);
    r = fmaf(kf, -1.42860676533018704e-06f, r);
    float p = 1.98412698412698413e-04f;
    p = fmaf(p, r, 1.38888888888888889e-03f);
    p = fmaf(p, r, 8.33333333333333333e-03f);
    p = fmaf(p, r, 4.16666666666666667e-02f);
    p = fmaf(p, r, 1.66666666666666667e-01f);
    p = fmaf(p, r, 0.5f);
    p = fmaf(p, r, 1.0f);
    p = fmaf(p, r, 1.0f);
    int ki = (int)kf;
    return p * __int_as_float((ki + 127) << 23);
}
__device__ __forceinline__ float warpMax(float v) {
#pragma unroll
    for (int o = 16; o; o >>= 1) v = fmaxf(v, __shfl_xor_sync(0xffffffffu, v, o));
    return v;
}
__device__ __forceinline__ float warpSum(float v) {
#pragma unroll
    for (int o = 16; o; o >>= 1) v += __shfl_xor_sync(0xffffffffu, v, o);
    return v;
}

// ---------------------------------------------------------------------------
// Fused GEMM + routing. CTA = 64 tokens x 256 experts, 256 threads (2x4 warps).
// Per-output k-order identical to certified round-8 kernel -> bitwise logits.
// 256 CTAs, 2/SM, one wave. Stage: BK=32 halves, rows padded to 80B.
// ---------------------------------------------------------------------------
#define ROWB    80
#define SROWS   640                   // 2*64 A rows + 2*256 B rows
#define STAGEB  (SROWS * ROWB)        // 51200 B
#define NKB     (HIDDEN / 32)         // 64 stages
#define SLSTR   258
#define DSMEM   (2 * STAGEB)          // 102400 B (>= 64*258*4 = 66048 for logits)

__global__ __launch_bounds__(256, 2) void fused_kernel(float* __restrict__ out) {
    extern __shared__ char dsm[];
    const uint32_t sbase = smem_u32(dsm);
    float* slog = (float*)dsm;

    const int tid    = threadIdx.x;
    const int lane   = tid & 31;
    const int wid    = tid >> 5;
    const int warp_m = wid & 1;      // 0..1 -> 32-token slab
    const int warp_n = wid >> 1;     // 0..3 -> 64-expert slab
    const int m0     = blockIdx.x * 64;

    // ---- loader: 2560 chunks (640 rows x 4 x 16B), 10 per thread ----
    uint32_t goff[10];
#pragma unroll
    for (int i = 0; i < 10; ++i) {
        int cid = tid + i * 256;
        int row = cid >> 2;
        int seg = cid & 3;
        size_t go;
        if (row < 128) {                 // A planes: 2 x 64 token rows
            int p = row >> 6, r = row & 63;
            go = (p ? XP1_OFF : XP0_OFF) + (size_t)(m0 + r) * HIDDEN + seg * 8;
        } else {                         // B planes: 2 x 256 expert rows
            int rr = row - 128;
            int q = rr >> 8, r = rr & 255;
            go = (q ? WP1_OFF : WP0_OFF) + (size_t)r * HIDDEN + seg * 8;
        }
        goff[i] = (uint32_t)(go * 2);    // bytes from g_planes
    }
    const char* gbase = (const char*)g_planes;

    float acc[2][8][4];
#pragma unroll
    for (int mf = 0; mf < 2; ++mf)
#pragma unroll
        for (int nf = 0; nf < 8; ++nf)
#pragma unroll
            for (int c = 0; c < 4; ++c) acc[mf][nf][c] = 0.f;

    const int a_row = lane & 15;
    const int a_col = (lane >> 4) << 3;
    const int b_row = ((lane >> 4) & 1) * 8 + (lane & 7);
    const int b_col = ((lane >> 3) & 1) * 8;

    // preload stage 0
#pragma unroll
    for (int i = 0; i < 10; ++i) {
        int cid = tid + i * 256;
        cp16s(sbase + (cid >> 2) * ROWB + (cid & 3) * 16, gbase + goff[i]);
    }
    asm volatile("cp.async.commit_group;");

    for (int kb = 0; kb < NKB; ++kb) {
        const uint32_t cur = sbase + (kb & 1) * STAGEB;
        asm volatile("cp.async.wait_group 0;");
        __syncthreads();
        if (kb + 1 < NKB) {
            const uint32_t nxt = sbase + ((kb + 1) & 1) * STAGEB;
            const uint32_t kadd = (uint32_t)(kb + 1) * 64;
#pragma unroll
            for (int i = 0; i < 10; ++i) {
                int cid = tid + i * 256;
                cp16s(nxt + (cid >> 2) * ROWB + (cid & 3) * 16, gbase + goff[i] + kadd);
            }
            asm volatile("cp.async.commit_group;");
        }

#pragma unroll
        for (int s = 0; s < 2; ++s) {
            uint32_t af[2][2][4];
#pragma unroll
            for (int p = 0; p < 2; ++p)
#pragma unroll
                for (int mf = 0; mf < 2; ++mf) {
                    uint32_t addr = cur
                                  + (p * 64 + warp_m * 32 + mf * 16 + a_row) * ROWB
                                  + (s * 16 + a_col) * 2;
                    ldsm4(af[p][mf], addr);
                }
#pragma unroll
            for (int pb = 0; pb < 2; ++pb) {
                uint32_t bf[4][4];
#pragma unroll
                for (int np = 0; np < 4; ++np) {
                    uint32_t addr = cur
                                  + (128 + pb * 256 + warp_n * 64 + np * 16 + b_row) * ROWB
                                  + (s * 16 + b_col) * 2;
                    ldsm4(bf[np], addr);
                }
                const int na = 2 - pb;
#pragma unroll
                for (int pa = 0; pa < 2; ++pa) {
                    if (pa >= na) break;
#pragma unroll
                    for (int mf = 0; mf < 2; ++mf)
#pragma unroll
                        for (int nf = 0; nf < 8; ++nf)
                            mma16816(acc[mf][nf], af[pa][mf], &bf[nf >> 1][(nf & 1) * 2]);
                }
            }
        }
    }

    // ---- epilogue: accs -> smem logits ----
    __syncthreads();
#pragma unroll
    for (int mf = 0; mf < 2; ++mf)
#pragma unroll
        for (int nf = 0; nf < 8; ++nf) {
            const int row = warp_m * 32 + mf * 16 + (lane >> 2);
            const int col = warp_n * 64 + nf * 8 + (lane & 3) * 2;
            *(float2*)&slog[(size_t)row * SLSTR + col] =
                make_float2(acc[mf][nf][0], acc[mf][nf][1]);
            *(float2*)&slog[(size_t)(row + 8) * SLSTR + col] =
                make_float2(acc[mf][nf][2], acc[mf][nf][3]);
        }
    __syncthreads();

    // ---- routing: 2 groups of 128 threads, 32 tokens each ----
    const int g  = tid >> 7;
    const int e  = tid & 127;
    const int gw = (tid >> 5) & 3;
    const int gl = tid & 31;

    __shared__ float s4g[2][4];
    __shared__ float sbg[2][NEXP];
    __shared__ float bvhlg[2][NEXP];
    __shared__ float candpg[2][NCAND];
    __shared__ float candflg[2][NCAND];
    __shared__ int   candeg[2][NCAND];
    __shared__ float candlg[2][NCAND];
    __shared__ float toppg[2][TOPK];
    __shared__ int   topeg[2][TOPK];

    for (int it = 0; it < 32; ++it) {
        const int t  = g * 32 + it;
        const int tg = m0 + t;
        float fl = slog[(size_t)t * SLSTR + e];
        float bl = slog[(size_t)t * SLSTR + 128 + e];

        float wm = warpMax(fl);
        if (gl == 0) s4g[g][gw] = wm;
        GBAR(g);
        float m1 = fmaxf(fmaxf(s4g[g][0], s4g[g][1]), fmaxf(s4g[g][2], s4g[g][3]));
        GBAR(g);
        float p = exp_precise(fl - m1);
        float wsum = warpSum(p);
        if (gl == 0) s4g[g][gw] = wsum;
        GBAR(g);
        float s1 = s4g[g][0] + s4g[g][1] + s4g[g][2] + s4g[g][3];
        GBAR(g);
        float prob = __fdiv_rn(p, s1);
        out[(size_t)tg * NEXP + e] = prob;

        wm = warpMax(bl);
        if (gl == 0) s4g[g][gw] = wm;
        GBAR(g);
        float m2 = fmaxf(fmaxf(s4g[g][0], s4g[g][1]), fmaxf(s4g[g][2], s4g[g][3]));
        GBAR(g);
        float q = exp_precise(bl - m2);
        wsum = warpSum(q);
        if (gl == 0) s4g[g][gw] = wsum;
        GBAR(g);
        float s2 = s4g[g][0] + s4g[g][1] + s4g[g][2] + s4g[g][3];
        float bprob = __fdiv_rn(q, s2);
        sbg[g][e] = bprob;
        GBAR(g);

        int r = 0;
#pragma unroll 8
        for (int j = 0; j < NEXP; ++j) {
            float v = sbg[g][j];
            r += (v > bprob) || (v == bprob && j < e);
        }
        bvhlg[g][r] = bl;
        if (r < NCAND) { candeg[g][r] = e; candpg[g][r] = prob; candflg[g][r] = fl; }
        GBAR(g);

        if (e < NCAND) {
            float cp = candpg[g][e];
            int r2 = 0;
#pragma unroll
            for (int j = 0; j < NCAND; ++j) {
                float v = candpg[g][j];
                r2 += (v > cp) || (v == cp && j < e);
            }
            candlg[g][r2] = candflg[g][e];
            if (r2 < TOPK) { topeg[g][r2] = candeg[g][e]; toppg[g][r2] = cp; }
        }
        GBAR(g);

        if (e == 0) {
            float s = 0.f;
#pragma unroll
            for (int k = 0; k < TOPK; ++k) s += toppg[g][k];
            float* ov = out + (size_t)TOKENS * NEXP + (size_t)tg * TOPK;
            float* oi = out + (size_t)TOKENS * NEXP + (size_t)TOKENS * TOPK + (size_t)tg * TOPK;
#pragma unroll
            for (int k = 0; k < TOPK; ++k) {
                ov[k] = __fdiv_rn(toppg[g][k], s);
                oi[k] = (float)topeg[g][k];
            }
            bool flag = (bvhlg[g][NCAND - 1] - bvhlg[g][NCAND] < TAU_L) ||
                        (candlg[g][TOPK - 1] - candlg[g][TOPK] < TAU_L);
#pragma unroll
            for (int k = 0; k < TOPK - 1; ++k)
                flag |= (candlg[g][k] - candlg[g][k + 1] < TAU_L);
            if (flag) {
                int pos = atomicAdd(&g_nflag, 1);
                g_flags[pos] = tg;
            }
        }
        GBAR(g);
    }
}

// ---------------------------------------------------------------------------
// Certified recompute (bitwise == round-2 chain, values staged through smem)
// + re-route, fused. One block (256 threads) per flagged token.
// ---------------------------------------------------------------------------
__global__ __launch_bounds__(256, 2) void recroute_kernel(const float* __restrict__ x,
                                                          float* __restrict__ out) {
    __shared__ float xs[HIDDEN];              // 8 KB
    __shared__ float ws[2][16 * NOUT];        // 32 KB
    __shared__ float sl[NOUT];
    __shared__ float s4[4];
    __shared__ float sb[NEXP];
    __shared__ float cand_p[NCAND];
    __shared__ int   cand_e[NCAND];
    __shared__ float top_p[TOPK];
    __shared__ int   top_e[TOPK];

    const int tid  = threadIdx.x;
    const int lane = tid & 31;
    const int wrp  = tid >> 5;
    const int cnt  = g_nflag;
    const uint32_t wsb0 = smem_u32(&ws[0][0]);
    const uint32_t wsb1 = smem_u32(&ws[1][0]);

    for (int i = blockIdx.x; i < cnt; i += gridDim.x) {
        const int t = g_flags[i];

        // stage x row (byte-copy; values identical)
        const float4* xrow = (const float4*)(x + (size_t)t * HIDDEN);
#pragma unroll
        for (int j = 0; j < 2; ++j)
            ((float4*)xs)[tid + j * 256] = xrow[tid + j * 256];

        // preload w stage 0 (contiguous 16 KB slab)
#pragma unroll
        for (int j = 0; j < 4; ++j) {
            int c = tid + j * 256;
            cp16s(wsb0 + c * 16, (const char*)g_wT + c * 16);
        }
        asm volatile("cp.async.commit_group;");

        float acc = 0.f, cmp = 0.f;
        const int n = tid;
        for (int kb = 0; kb < NKB * 2; ++kb) {     // 128 stages of 16 k
            const float* wcur = ws[kb & 1];
            asm volatile("cp.async.wait_group 0;");
            __syncthreads();
            if (kb + 1 < NKB * 2) {
                uint32_t nb = (kb + 1) & 1 ? wsb1 : wsb0;
                const char* gsrc = (const char*)g_wT + (size_t)(kb + 1) * 16384;
#pragma unroll
                for (int j = 0; j < 4; ++j) {
                    int c = tid + j * 256;
                    cp16s(nb + c * 16, gsrc + c * 16);
                }
                asm volatile("cp.async.commit_group;");
            }
            // certified 16-term block partial + Kahan merge (op-identical)
            float bp = 0.f;
#pragma unroll
            for (int k = 0; k < 16; ++k)
                bp = fmaf(xs[kb * 16 + k], wcur[k * NOUT + n], bp);
            float y = bp - cmp;
            float s = acc + y;
            cmp = (s - acc) - y;
            acc = s;
            __syncthreads();
        }
        sl[n] = acc;
        __syncthreads();

        // ---- route (threads 0..127 active; all hit barriers) ----
        float fl = sl[tid & 127];
        float bl = sl[128 + (tid & 127)];
        const int e = tid & 127;
        const bool active = tid < 128;

        float wm = active ? warpMax(fl) : 0.f;
        if (active && lane == 0) s4[wrp] = wm;
        __syncthreads();
        float m1 = fmaxf(fmaxf(s4[0], s4[1]), fmaxf(s4[2], s4[3]));
        __syncthreads();
        float p = exp_precise(fl - m1);
        float wsum = active ? warpSum(p) : 0.f;
        if (active && lane == 0) s4[wrp] = wsum;
        __syncthreads();
        float s1 = s4[0] + s4[1] + s4[2] + s4[3];
        __syncthreads();
        float prob = __fdiv_rn(p, s1);
        if (active) out[(size_t)t * NEXP + e] = prob;

        wm = active ? warpMax(bl) : 0.f;
        if (active && lane == 0) s4[wrp] = wm;
        __syncthreads();
        float m2 = fmaxf(fmaxf(s4[0], s4[1]), fmaxf(s4[2], s4[3]));
        __syncthreads();
        float q = exp_precise(bl - m2);
        wsum = active ? warpSum(q) : 0.f;
        if (active && lane == 0) s4[wrp] = wsum;
        __syncthreads();
        float s2 = s4[0] + s4[1] + s4[2] + s4[3];
        float bprob = __fdiv_rn(q, s2);
        if (active) sb[e] = bprob;
        __syncthreads();

        if (active) {
            int r = 0;
#pragma unroll 8
            for (int j = 0; j < NEXP; ++j) {
                float v = sb[j];
                r += (v > bprob) || (v == bprob && j < e);
            }
            if (r < NCAND) { cand_e[r] = e; cand_p[r] = prob; }
        }
        __syncthreads();

        if (tid < NCAND) {
            float cp = cand_p[tid];
            int r2 = 0;
#pragma unroll
            for (int j = 0; j < NCAND; ++j) {
                float v = cand_p[j];
                r2 += (v > cp) || (v == cp && j < tid);
            }
            if (r2 < TOPK) { top_e[r2] = cand_e[tid]; top_p[r2] = cp; }
        }
        __syncthreads();

        if (tid == 0) {
            float s = 0.f;
#pragma unroll
            for (int k = 0; k < TOPK; ++k) s += top_p[k];
            float* ov = out + (size_t)TOKENS * NEXP + (size_t)t * TOPK;
            float* oi = out + (size_t)TOKENS * NEXP + (size_t)TOKENS * TOPK + (size_t)t * TOPK;
#pragma unroll
            for (int k = 0; k < TOPK; ++k) {
                ov[k] = __fdiv_rn(top_p[k], s);
                oi[k] = (float)top_e[k];
            }
        }
        __syncthreads();
    }
}

// ---------------------------------------------------------------------------
extern "C" void kernel_launch(void* const* d_in, const int* in_sizes, int n_in,
                              void* d_out, int out_size) {
    const float* x  = (const float*)d_in[0];
    const float* wo = (const float*)d_in[1];
    const float* wb = (const float*)d_in[2];
    float* out = (float*)d_out;

    cudaFuncSetAttribute(fused_kernel, cudaFuncAttributeMaxDynamicSharedMemorySize, DSMEM);

    wprep_kernel<<<(NOUT * HIDDEN / 4 + 255) / 256, 256>>>(wo, wb);
    xsplit_kernel<<<TOKENS * HIDDEN / 4 / 256, 256>>>(x);
    fused_kernel<<<TOKENS / 64, 256, DSMEM>>>(out);
    recroute_kernel<<<512, 256>>>(x, out);
}

// round 11
// speedup vs baseline: 1.3572x; 1.0832x over previous
#include <cuda_runtime.h>
#include <cuda_fp16.h>
#include <cstdint>

#define TOKENS 16384
#define HIDDEN 2048
#define NEXP   128
#define NOUT   256
#define TOPK   8
#define NCAND  32
#define TAU_L  6e-5f

typedef unsigned long long u64;

// ---------------- scratch (no allocs allowed) ----------------
__device__ float g_wT[HIDDEN * NOUT];        // [h][n] fp32 (certified recompute)
// w planes packed: wp0 | wp1
#define WP0_OFF 0
#define WP1_OFF ((size_t)NOUT * HIDDEN)
__device__ __half g_planes[2 * (size_t)NOUT * HIDDEN];
__device__ int g_nflag;
__device__ int g_flags[TOKENS];

// ---------------- PTX helpers (baseline ISA only) ----------------
__device__ __forceinline__ uint32_t smem_u32(const void* p) {
    uint32_t a;
    asm("{ .reg .u64 t; cvta.to.shared.u64 t, %1; cvt.u32.u64 %0, t; }" : "=r"(a) : "l"(p));
    return a;
}
__device__ __forceinline__ void cp16s(uint32_t saddr, const void* g) {
    asm volatile("cp.async.cg.shared.global [%0], [%1], 16;" :: "r"(saddr), "l"(g));
}
__device__ __forceinline__ void ldsm4(uint32_t* r, uint32_t a) {
    asm volatile("ldmatrix.sync.aligned.m8n8.x4.shared.b16 {%0,%1,%2,%3}, [%4];"
                 : "=r"(r[0]), "=r"(r[1]), "=r"(r[2]), "=r"(r[3]) : "r"(a));
}
__device__ __forceinline__ void mma16816(float* d, const uint32_t* a, const uint32_t* b) {
    asm volatile(
        "mma.sync.aligned.m16n8k16.row.col.f32.f16.f16.f32 "
        "{%0,%1,%2,%3}, {%4,%5,%6,%7}, {%8,%9}, {%0,%1,%2,%3};"
        : "+f"(d[0]), "+f"(d[1]), "+f"(d[2]), "+f"(d[3])
        : "r"(a[0]), "r"(a[1]), "r"(a[2]), "r"(a[3]), "r"(b[0]), "r"(b[1]));
}
#define GBAR(g) asm volatile("bar.sync %0, %1;" :: "r"((g) + 1), "r"(128) : "memory")

// fp16 2-plane split: v = p0 + p1 + O(2^-22 v)
__device__ __forceinline__ void split2(float v, __half& a0, __half& a1) {
    a0 = __float2half_rn(v);
    a1 = __float2half_rn(v - __half2float(a0));
}

// ---------------------------------------------------------------------------
// Weight prep: fp16 planes + fp32 transpose + flag reset
// ---------------------------------------------------------------------------
__global__ void wprep_kernel(const float* __restrict__ wo,
                             const float* __restrict__ wb) {
    if (blockIdx.x == 0 && threadIdx.x == 0) g_nflag = 0;
    size_t i4 = (size_t)blockIdx.x * 256 + threadIdx.x;
    if (i4 >= (size_t)NOUT * HIDDEN / 4) return;
    int n  = (int)(i4 / (HIDDEN / 4));
    int c4 = (int)(i4 % (HIDDEN / 4)) * 4;
    const float* src = (n < NEXP) ? &wo[(size_t)n * HIDDEN + c4]
                                  : &wb[(size_t)(n - NEXP) * HIDDEN + c4];
    float4 v = *(const float4*)src;
    __half a0[4], a1[4];
    split2(v.x, a0[0], a1[0]);
    split2(v.y, a0[1], a1[1]);
    split2(v.z, a0[2], a1[2]);
    split2(v.w, a0[3], a1[3]);
    size_t e = (size_t)n * HIDDEN + c4;
    *(uint2*)&g_planes[WP0_OFF + e] = *(uint2*)a0;
    *(uint2*)&g_planes[WP1_OFF + e] = *(uint2*)a1;
    g_wT[(size_t)(c4 + 0) * NOUT + n] = v.x;
    g_wT[(size_t)(c4 + 1) * NOUT + n] = v.y;
    g_wT[(size_t)(c4 + 2) * NOUT + n] = v.z;
    g_wT[(size_t)(c4 + 3) * NOUT + n] = v.w;
}

// ---------------------------------------------------------------------------
// Precise exp + warp reductions
// ---------------------------------------------------------------------------
__device__ __forceinline__ float exp_precise(float xx) {
    float kf = rintf(xx * 1.4426950408889634f);
    float r  = fmaf(kf, -0.693145751953125f, xx);
    r = fmaf(kf, -1.42860676533018704e-06f, r);
    float p = 1.98412698412698413e-04f;
    p = fmaf(p, r, 1.38888888888888889e-03f);
    p = fmaf(p, r, 8.33333333333333333e-03f);
    p = fmaf(p, r, 4.16666666666666667e-02f);
    p = fmaf(p, r, 1.66666666666666667e-01f);
    p = fmaf(p, r, 0.5f);
    p = fmaf(p, r, 1.0f);
    p = fmaf(p, r, 1.0f);
    int ki = (int)kf;
    return p * __int_as_float((ki + 127) << 23);
}
__device__ __forceinline__ float warpMax(float v) {
#pragma unroll
    for (int o = 16; o; o >>= 1) v = fmaxf(v, __shfl_xor_sync(0xffffffffu, v, o));
    return v;
}
__device__ __forceinline__ float warpSum(float v) {
#pragma unroll
    for (int o = 16; o; o >>= 1) v += __shfl_xor_sync(0xffffffffu, v, o);
    return v;
}

// ---------------------------------------------------------------------------
// Fused GEMM + routing. CTA = 64 tokens x 256 experts, 256 threads (2x4 warps).
// x loaded as RAW fp32 and split to fp16 planes in-kernel (bitwise == xsplit).
// Stage layout (80B rows): rows 0-63 = A plane0, 64-127 = A plane1,
// 128-639 = B planes (2x256). x32 staging buffer is separate (single).
// ---------------------------------------------------------------------------
#define ROWB    80
#define STAGEB  (640 * ROWB)          // 51200 B
#define X32OFF  (2 * STAGEB)          // 102400
#define NKB     (HIDDEN / 32)         // 64 stages
#define SLSTR   258
#define DSMEM   (X32OFF + 64 * 128)   // 110592 B

__global__ __launch_bounds__(256, 2) void fused_kernel(const float* __restrict__ x,
                                                       float* __restrict__ out) {
    extern __shared__ char dsm[];
    const uint32_t sbase = smem_u32(dsm);
    const uint32_t x32b  = sbase + X32OFF;
    float* slog = (float*)dsm;

    const int tid    = threadIdx.x;
    const int lane   = tid & 31;
    const int wid    = tid >> 5;
    const int warp_m = wid & 1;
    const int warp_n = wid >> 1;
    const int m0     = blockIdx.x * 64;

    // ---- loader setup: i 0..7 = B chunks, i 8..9 = x32 chunks ----
    uint32_t smoffB[8], goffB[8], smoffX[2], goffX[2];
#pragma unroll
    for (int i = 0; i < 8; ++i) {
        int cid = tid + i * 256;                 // 0..2047
        int row = cid >> 2, seg = cid & 3;       // row 0..511
        smoffB[i] = (uint32_t)((128 + row) * ROWB + seg * 16);
        int q = row >> 8, r = row & 255;
        goffB[i] = (uint32_t)(((q ? WP1_OFF : WP0_OFF) + (size_t)r * HIDDEN) * 2 + seg * 16);
    }
#pragma unroll
    for (int i = 0; i < 2; ++i) {
        int c = tid + i * 256;                   // 0..511
        int row = c >> 3, seg = c & 7;
        smoffX[i] = (uint32_t)(row * 128 + seg * 16);
        goffX[i]  = (uint32_t)((size_t)(m0 + row) * HIDDEN * 4 + seg * 16);
    }
    const char* gw = (const char*)g_planes;
    const char* gx = (const char*)x;

    float acc[2][8][4];
#pragma unroll
    for (int mf = 0; mf < 2; ++mf)
#pragma unroll
        for (int nf = 0; nf < 8; ++nf)
#pragma unroll
            for (int c = 0; c < 4; ++c) acc[mf][nf][c] = 0.f;

    const int a_row = lane & 15;
    const int a_col = (lane >> 4) << 3;
    const int b_row = ((lane >> 4) & 1) * 8 + (lane & 7);
    const int b_col = ((lane >> 3) & 1) * 8;

    // preload stage 0
#pragma unroll
    for (int i = 0; i < 8; ++i) cp16s(sbase + smoffB[i], gw + goffB[i]);
#pragma unroll
    for (int i = 0; i < 2; ++i) cp16s(x32b + smoffX[i], gx + goffX[i]);
    asm volatile("cp.async.commit_group;");

    for (int kb = 0; kb < NKB; ++kb) {
        const uint32_t cur = sbase + (kb & 1) * STAGEB;
        char* curp = dsm + (kb & 1) * STAGEB;
        asm volatile("cp.async.wait_group 0;");
        __syncthreads();

        // ---- convert x32 -> A planes (bitwise == xsplit_kernel) ----
        {
            const float2* xf2 = (const float2*)(dsm + X32OFF);
#pragma unroll
            for (int i = 0; i < 4; ++i) {
                int pi = tid + i * 256;          // 0..1023
                int r = pi >> 4, kk2 = pi & 15;
                float2 v = xf2[pi];
                __half a0x, a1x, a0y, a1y;
                split2(v.x, a0x, a1x);
                split2(v.y, a0y, a1y);
                *(__half2*)(curp + r * ROWB + kk2 * 4)        = __halves2half2(a0x, a0y);
                *(__half2*)(curp + (64 + r) * ROWB + kk2 * 4) = __halves2half2(a1x, a1y);
            }
        }
        __syncthreads();

        if (kb + 1 < NKB) {
            const uint32_t nxt = sbase + ((kb + 1) & 1) * STAGEB;
            const uint32_t kb1 = (uint32_t)(kb + 1);
#pragma unroll
            for (int i = 0; i < 8; ++i) cp16s(nxt + smoffB[i], gw + goffB[i] + kb1 * 64);
#pragma unroll
            for (int i = 0; i < 2; ++i) cp16s(x32b + smoffX[i], gx + goffX[i] + kb1 * 128);
            asm volatile("cp.async.commit_group;");
        }

#pragma unroll
        for (int s = 0; s < 2; ++s) {
            uint32_t af[2][2][4];
#pragma unroll
            for (int p = 0; p < 2; ++p)
#pragma unroll
                for (int mf = 0; mf < 2; ++mf) {
                    uint32_t addr = cur
                                  + (p * 64 + warp_m * 32 + mf * 16 + a_row) * ROWB
                                  + (s * 16 + a_col) * 2;
                    ldsm4(af[p][mf], addr);
                }
#pragma unroll
            for (int pb = 0; pb < 2; ++pb) {
                uint32_t bf[4][4];
#pragma unroll
                for (int np = 0; np < 4; ++np) {
                    uint32_t addr = cur
                                  + (128 + pb * 256 + warp_n * 64 + np * 16 + b_row) * ROWB
                                  + (s * 16 + b_col) * 2;
                    ldsm4(bf[np], addr);
                }
                const int na = 2 - pb;
#pragma unroll
                for (int pa = 0; pa < 2; ++pa) {
                    if (pa >= na) break;
#pragma unroll
                    for (int mf = 0; mf < 2; ++mf)
#pragma unroll
                        for (int nf = 0; nf < 8; ++nf)
                            mma16816(acc[mf][nf], af[pa][mf], &bf[nf >> 1][(nf & 1) * 2]);
                }
            }
        }
    }

    // ---- epilogue: accs -> smem logits ----
    __syncthreads();
#pragma unroll
    for (int mf = 0; mf < 2; ++mf)
#pragma unroll
        for (int nf = 0; nf < 8; ++nf) {
            const int row = warp_m * 32 + mf * 16 + (lane >> 2);
            const int col = warp_n * 64 + nf * 8 + (lane & 3) * 2;
            *(float2*)&slog[(size_t)row * SLSTR + col] =
                make_float2(acc[mf][nf][0], acc[mf][nf][1]);
            *(float2*)&slog[(size_t)(row + 8) * SLSTR + col] =
                make_float2(acc[mf][nf][2], acc[mf][nf][3]);
        }
    __syncthreads();

    // ---- routing: 2 groups of 128 threads, 32 tokens each; merged reductions ----
    const int g  = tid >> 7;
    const int e  = tid & 127;
    const int gw2 = (tid >> 5) & 3;
    const int gl = tid & 31;

    __shared__ float s4m1[2][4], s4m2[2][4], s4s1[2][4], s4s2[2][4];
    __shared__ float sbg[2][NEXP];
    __shared__ float bvhlg[2][NEXP];
    __shared__ float candpg[2][NCAND];
    __shared__ float candflg[2][NCAND];
    __shared__ int   candeg[2][NCAND];
    __shared__ float candlg[2][NCAND];
    __shared__ float toppg[2][TOPK];
    __shared__ int   topeg[2][TOPK];

    for (int it = 0; it < 32; ++it) {
        const int t  = g * 32 + it;
        const int tg = m0 + t;
        float fl = slog[(size_t)t * SLSTR + e];
        float bl = slog[(size_t)t * SLSTR + 128 + e];

        float wm1 = warpMax(fl);
        float wm2 = warpMax(bl);
        if (gl == 0) { s4m1[g][gw2] = wm1; s4m2[g][gw2] = wm2; }
        GBAR(g);
        float m1 = fmaxf(fmaxf(s4m1[g][0], s4m1[g][1]), fmaxf(s4m1[g][2], s4m1[g][3]));
        float m2 = fmaxf(fmaxf(s4m2[g][0], s4m2[g][1]), fmaxf(s4m2[g][2], s4m2[g][3]));
        float p = exp_precise(fl - m1);
        float q = exp_precise(bl - m2);
        float ws1 = warpSum(p);
        float ws2 = warpSum(q);
        if (gl == 0) { s4s1[g][gw2] = ws1; s4s2[g][gw2] = ws2; }
        GBAR(g);
        float s1 = s4s1[g][0] + s4s1[g][1] + s4s1[g][2] + s4s1[g][3];
        float s2 = s4s2[g][0] + s4s2[g][1] + s4s2[g][2] + s4s2[g][3];
        float prob  = __fdiv_rn(p, s1);
        out[(size_t)tg * NEXP + e] = prob;
        float bprob = __fdiv_rn(q, s2);
        sbg[g][e] = bprob;
        GBAR(g);

        int r = 0;
#pragma unroll 8
        for (int j = 0; j < NEXP; ++j) {
            float v = sbg[g][j];
            r += (v > bprob) || (v == bprob && j < e);
        }
        bvhlg[g][r] = bl;
        if (r < NCAND) { candeg[g][r] = e; candpg[g][r] = prob; candflg[g][r] = fl; }
        GBAR(g);

        if (e < NCAND) {
            float cp = candpg[g][e];
            int r2 = 0;
#pragma unroll
            for (int j = 0; j < NCAND; ++j) {
                float v = candpg[g][j];
                r2 += (v > cp) || (v == cp && j < e);
            }
            candlg[g][r2] = candflg[g][e];
            if (r2 < TOPK) { topeg[g][r2] = candeg[g][e]; toppg[g][r2] = cp; }
        }
        GBAR(g);

        if (e == 0) {
            float s = 0.f;
#pragma unroll
            for (int k = 0; k < TOPK; ++k) s += toppg[g][k];
            float* ov = out + (size_t)TOKENS * NEXP + (size_t)tg * TOPK;
            float* oi = out + (size_t)TOKENS * NEXP + (size_t)TOKENS * TOPK + (size_t)tg * TOPK;
#pragma unroll
            for (int k = 0; k < TOPK; ++k) {
                ov[k] = __fdiv_rn(toppg[g][k], s);
                oi[k] = (float)topeg[g][k];
            }
            bool flag = (bvhlg[g][NCAND - 1] - bvhlg[g][NCAND] < TAU_L) ||
                        (candlg[g][TOPK - 1] - candlg[g][TOPK] < TAU_L);
#pragma unroll
            for (int k = 0; k < TOPK - 1; ++k)
                flag |= (candlg[g][k] - candlg[g][k + 1] < TAU_L);
            if (flag) {
                int pos = atomicAdd(&g_nflag, 1);
                g_flags[pos] = tg;
            }
        }
        GBAR(g);
    }
}

// ---------------------------------------------------------------------------
// Certified recompute + re-route, 4 tokens per block.
// Thread = (token j, 4 consecutive experts). Chain per (t,n) is op-identical
// to the certified round-2 ordering. 3-buffer w ring, depth-2 prefetch.
// Dynamic smem: xs 32768 | ws 3*16384 | sl 4096  = 86016 B
// ---------------------------------------------------------------------------
#define RC_XS   0
#define RC_WS   32768
#define RC_SL   (32768 + 49152)
#define RC_SMEM (RC_SL + 4096)

__global__ __launch_bounds__(256, 2) void recroute_kernel(const float* __restrict__ x,
                                                          float* __restrict__ out) {
    extern __shared__ char rsm[];
    float* xs = (float*)(rsm + RC_XS);          // [4][2048]
    float* wsm = (float*)(rsm + RC_WS);         // [3][16*256]
    float* sl = (float*)(rsm + RC_SL);          // [4][256]
    const uint32_t xsb = smem_u32(xs);
    const uint32_t wsb = smem_u32(wsm);

    __shared__ float s4[4];
    __shared__ float sb[NEXP];
    __shared__ float cand_p[NCAND];
    __shared__ int   cand_e[NCAND];
    __shared__ float top_p[TOPK];
    __shared__ int   top_e[TOPK];

    const int tid  = threadIdx.x;
    const int lane = tid & 31;
    const int wrp  = tid >> 5;
    const int cnt  = g_nflag;
    const int ngroups = (cnt + 3) >> 2;
    const int j   = tid >> 6;          // token slot 0..3
    const int n4  = (tid & 63) * 4;    // 4 consecutive experts

    for (int gi = blockIdx.x; gi < ngroups; gi += gridDim.x) {
        int tlist[4];
#pragma unroll
        for (int j2 = 0; j2 < 4; ++j2) {
            int idx = gi * 4 + j2;
            tlist[j2] = g_flags[idx < cnt ? idx : cnt - 1];
        }

        // drain any in-flight loads from the previous group, then stage
        asm volatile("cp.async.wait_group 0;");
        __syncthreads();

        // xs: 4 rows x 8 KB = 2048 chunks
#pragma unroll
        for (int i = 0; i < 8; ++i) {
            int cid = tid + i * 256;
            int j2 = cid >> 9, c = cid & 511;
            cp16s(xsb + j2 * 8192 + c * 16,
                  (const char*)(x + (size_t)tlist[j2] * HIDDEN) + c * 16);
        }
        // w stage 0 (same commit group as xs)
#pragma unroll
        for (int i = 0; i < 4; ++i) {
            int cid = tid + i * 256;
            cp16s(wsb + cid * 16, (const char*)g_wT + cid * 16);
        }
        asm volatile("cp.async.commit_group;");
        // w stage 1
#pragma unroll
        for (int i = 0; i < 4; ++i) {
            int cid = tid + i * 256;
            cp16s(wsb + 16384 + cid * 16, (const char*)g_wT + 16384 + cid * 16);
        }
        asm volatile("cp.async.commit_group;");

        float acc[4] = {0.f, 0.f, 0.f, 0.f};
        float cmp[4] = {0.f, 0.f, 0.f, 0.f};

        for (int kb = 0; kb < 128; ++kb) {
            asm volatile("cp.async.wait_group 1;");
            __syncthreads();
            if (kb + 2 < 128) {
                uint32_t buf = (uint32_t)((kb + 2) % 3) * 16384;
                const char* gsrc = (const char*)g_wT + (size_t)(kb + 2) * 16384;
#pragma unroll
                for (int i = 0; i < 4; ++i) {
                    int cid = tid + i * 256;
                    cp16s(wsb + buf + cid * 16, gsrc + cid * 16);
                }
                asm volatile("cp.async.commit_group;");
            }
            const float* wcur = wsm + (kb % 3) * 4096;
            const float* xrow = xs + j * 2048 + kb * 16;
            float bp[4] = {0.f, 0.f, 0.f, 0.f};
#pragma unroll
            for (int k = 0; k < 16; ++k) {
                float xv = xrow[k];
                float4 w4 = *(const float4*)&wcur[k * NOUT + n4];
                bp[0] = fmaf(xv, w4.x, bp[0]);
                bp[1] = fmaf(xv, w4.y, bp[1]);
                bp[2] = fmaf(xv, w4.z, bp[2]);
                bp[3] = fmaf(xv, w4.w, bp[3]);
            }
#pragma unroll
            for (int c = 0; c < 4; ++c) {
                float y = bp[c] - cmp[c];
                float s = acc[c] + y;
                cmp[c] = (s - acc[c]) - y;
                acc[c] = s;
            }
        }
#pragma unroll
        for (int c = 0; c < 4; ++c) sl[j * 256 + n4 + c] = acc[c];
        __syncthreads();

        // ---- route the (up to) 4 tokens sequentially ----
        for (int j2 = 0; j2 < 4; ++j2) {
            if (gi * 4 + j2 >= cnt) break;     // uniform across block
            const int t = tlist[j2];
            const float* slj = sl + j2 * 256;
            const int e = tid & 127;
            const bool active = tid < 128;
            float fl = slj[e];
            float bl = slj[128 + e];

            float wm = active ? warpMax(fl) : 0.f;
            if (active && lane == 0) s4[wrp] = wm;
            __syncthreads();
            float m1 = fmaxf(fmaxf(s4[0], s4[1]), fmaxf(s4[2], s4[3]));
            __syncthreads();
            float p = exp_precise(fl - m1);
            float wsum = active ? warpSum(p) : 0.f;
            if (active && lane == 0) s4[wrp] = wsum;
            __syncthreads();
            float s1 = s4[0] + s4[1] + s4[2] + s4[3];
            __syncthreads();
            float prob = __fdiv_rn(p, s1);
            if (active) out[(size_t)t * NEXP + e] = prob;

            wm = active ? warpMax(bl) : 0.f;
            if (active && lane == 0) s4[wrp] = wm;
            __syncthreads();
            float m2 = fmaxf(fmaxf(s4[0], s4[1]), fmaxf(s4[2], s4[3]));
            __syncthreads();
            float q = exp_precise(bl - m2);
            wsum = active ? warpSum(q) : 0.f;
            if (active && lane == 0) s4[wrp] = wsum;
            __syncthreads();
            float s2 = s4[0] + s4[1] + s4[2] + s4[3];
            float bprob = __fdiv_rn(q, s2);
            if (active) sb[e] = bprob;
            __syncthreads();

            if (active) {
                int r = 0;
#pragma unroll 8
                for (int jj = 0; jj < NEXP; ++jj) {
                    float v = sb[jj];
                    r += (v > bprob) || (v == bprob && jj < e);
                }
                if (r < NCAND) { cand_e[r] = e; cand_p[r] = prob; }
            }
            __syncthreads();

            if (tid < NCAND) {
                float cp = cand_p[tid];
                int r2 = 0;
#pragma unroll
                for (int jj = 0; jj < NCAND; ++jj) {
                    float v = cand_p[jj];
                    r2 += (v > cp) || (v == cp && jj < tid);
                }
                if (r2 < TOPK) { top_e[r2] = cand_e[tid]; top_p[r2] = cp; }
            }
            __syncthreads();

            if (tid == 0) {
                float s = 0.f;
#pragma unroll
                for (int k = 0; k < TOPK; ++k) s += top_p[k];
                float* ov = out + (size_t)TOKENS * NEXP + (size_t)t * TOPK;
                float* oi = out + (size_t)TOKENS * NEXP + (size_t)TOKENS * TOPK + (size_t)t * TOPK;
#pragma unroll
                for (int k = 0; k < TOPK; ++k) {
                    ov[k] = __fdiv_rn(top_p[k], s);
                    oi[k] = (float)top_e[k];
                }
            }
            __syncthreads();
        }
    }
}

// ---------------------------------------------------------------------------
extern "C" void kernel_launch(void* const* d_in, const int* in_sizes, int n_in,
                              void* d_out, int out_size) {
    const float* x  = (const float*)d_in[0];
    const float* wo = (const float*)d_in[1];
    const float* wb = (const float*)d_in[2];
    float* out = (float*)d_out;

    cudaFuncSetAttribute(fused_kernel, cudaFuncAttributeMaxDynamicSharedMemorySize, DSMEM);
    cudaFuncSetAttribute(recroute_kernel, cudaFuncAttributeMaxDynamicSharedMemorySize, RC_SMEM);

    wprep_kernel<<<(NOUT * HIDDEN / 4 + 255) / 256, 256>>>(wo, wb);
    fused_kernel<<<TOKENS / 64, 256, DSMEM>>>(x, out);
    recroute_kernel<<<512, 256, RC_SMEM>>>(x, out);
}